// round 10
// baseline (speedup 1.0000x reference)
#include <cuda_runtime.h>
#include <cuda_bf16.h>
#include <math.h>
#include <stdint.h>

// Problem constants (shapes fixed by the dataset).
#define DIM   256
#define MAXN  100000
#define MAXE  800000
#define SCANB 1024
#define MAXBLK 128          // >= ceil(MAXN/SCANB) = 98

// -------- device-global scratch (allocation-free workaround) --------
__device__ float g_support[MAXN * DIM];                    // x @ W
__device__ __align__(16) __nv_bfloat16 g_Xh[MAXN * DIM];   // bf16 hi of X
__device__ __align__(16) __nv_bfloat16 g_Xl[MAXN * DIM];   // bf16 lo of X
__device__ __align__(16) __nv_bfloat16 g_Wh[DIM * DIM];    // bf16 hi of W^T: [n][k]
__device__ __align__(16) __nv_bfloat16 g_Wl[DIM * DIM];    // bf16 lo of W^T
__device__ int   g_counts[MAXN];
__device__ int   g_scan[MAXN];
__device__ int   g_rowptr[MAXN + 1];
__device__ int   g_cursor[MAXN];
__device__ int   g_bsum[MAXBLK];
__device__ int   g_esrc[MAXE];
__device__ float g_eval[MAXE];

__device__ __forceinline__ uint32_t pack_bf16(float a, float b) {
    __nv_bfloat162 h = __floats2bfloat162_rn(a, b);
    return *reinterpret_cast<uint32_t*>(&h);
}
__device__ __forceinline__ float bf16_hi_f(float a) {
    return __bfloat162float(__float2bfloat16_rn(a));
}

// ---------------- Pre-conversion ----------------
// X -> hi/lo bf16, 8 elements per thread (one uint4 store each).
__global__ void k_convert_x(const float* __restrict__ X, int total8) {
    int i = blockIdx.x * blockDim.x + threadIdx.x;
    if (i >= total8) return;
    const float4* src = reinterpret_cast<const float4*>(X) + 2 * (size_t)i;
    float4 x0 = src[0];
    float4 x1 = src[1];
    float v[8] = {x0.x, x0.y, x0.z, x0.w, x1.x, x1.y, x1.z, x1.w};
    uint32_t h[4], l[4];
    #pragma unroll
    for (int j = 0; j < 4; j++) {
        float h0 = bf16_hi_f(v[2 * j]);
        float h1 = bf16_hi_f(v[2 * j + 1]);
        h[j] = pack_bf16(h0, h1);
        l[j] = pack_bf16(v[2 * j] - h0, v[2 * j + 1] - h1);
    }
    reinterpret_cast<uint4*>(g_Xh)[i] = make_uint4(h[0], h[1], h[2], h[3]);
    reinterpret_cast<uint4*>(g_Xl)[i] = make_uint4(l[0], l[1], l[2], l[3]);
}

// W [k][n] -> W^T hi/lo bf16 [n][k]. 256 blocks (n) x 256 threads (k). Tiny.
__global__ void k_convert_w(const float* __restrict__ W) {
    int n = blockIdx.x;
    int k = threadIdx.x;
    float v = W[(size_t)k * DIM + n];
    float h = bf16_hi_f(v);
    g_Wh[(size_t)n * DIM + k] = __float2bfloat16_rn(h);
    g_Wl[(size_t)n * DIM + k] = __float2bfloat16_rn(v - h);
}

// ---------------- CSR construction ----------------
__global__ void k_zero_counts(int n) {
    int i = blockIdx.x * blockDim.x + threadIdx.x;
    if (i < n) g_counts[i] = 0;
}

__global__ void k_hist(const int* __restrict__ dst, int E) {
    int e = blockIdx.x * blockDim.x + threadIdx.x;
    if (e < E) atomicAdd(&g_counts[dst[e]], 1);
}

__global__ void k_scan_block(int n) {
    __shared__ int s[SCANB];
    int t = threadIdx.x;
    int gid = blockIdx.x * SCANB + t;
    int v = (gid < n) ? g_counts[gid] : 0;
    s[t] = v;
    __syncthreads();
    #pragma unroll
    for (int off = 1; off < SCANB; off <<= 1) {
        int x = (t >= off) ? s[t - off] : 0;
        __syncthreads();
        s[t] += x;
        __syncthreads();
    }
    if (gid < n) g_scan[gid] = s[t];
    if (t == SCANB - 1) g_bsum[blockIdx.x] = s[t];
}

__global__ void k_scan_sums(int nb) {
    __shared__ int s[MAXBLK];
    int t = threadIdx.x;                 // 128 threads
    int v = (t < nb) ? g_bsum[t] : 0;
    s[t] = v;
    __syncthreads();
    #pragma unroll
    for (int off = 1; off < MAXBLK; off <<= 1) {
        int x = (t >= off) ? s[t - off] : 0;
        __syncthreads();
        s[t] += x;
        __syncthreads();
    }
    if (t < nb) g_bsum[t] = s[t] - v;    // exclusive
}

__global__ void k_finalize_rowptr(int n) {
    int i = blockIdx.x * blockDim.x + threadIdx.x;
    if (i < n) {
        g_rowptr[i + 1] = g_scan[i] + g_bsum[i >> 10];
        int rp0 = (i == 0) ? 0 : (g_scan[i - 1] + g_bsum[(i - 1) >> 10]);
        g_cursor[i] = rp0;
        if (i == 0) g_rowptr[0] = 0;
    }
}

__global__ void k_fill(const int* __restrict__ dst, const int* __restrict__ src,
                       const float* __restrict__ av, const float* __restrict__ aw, int E) {
    int e = blockIdx.x * blockDim.x + threadIdx.x;
    if (e < E) {
        int d = dst[e];
        int p = atomicAdd(&g_cursor[d], 1);
        g_esrc[p] = src[e];
        g_eval[p] = av[e] + aw[e];
    }
}

// ---------------- GEMM: support = x @ W  (3xBF16 + ldmatrix, preconverted) ----
// 128x128 block tile, BK=32, 256 threads = 8 warps in 2(M) x 4(N).
// Loaders are pure 16B copies from g_Xh/g_Xl/g_Wh/g_Wl.

__device__ __forceinline__ uint32_t smem_u32(const void* p) {
    uint32_t a;
    asm("{ .reg .u64 t; cvta.to.shared.u64 t, %1; cvt.u32.u64 %0, t; }" : "=r"(a) : "l"(p));
    return a;
}

__device__ __forceinline__ void ldsm_x4(uint32_t& r0, uint32_t& r1, uint32_t& r2, uint32_t& r3,
                                        uint32_t addr) {
    asm volatile("ldmatrix.sync.aligned.m8n8.x4.shared.b16 {%0,%1,%2,%3}, [%4];"
                 : "=r"(r0), "=r"(r1), "=r"(r2), "=r"(r3) : "r"(addr));
}

__device__ __forceinline__ void mma_bf16(float c[4], uint32_t a0, uint32_t a1,
                                         uint32_t a2, uint32_t a3,
                                         uint32_t b0, uint32_t b1) {
    asm volatile(
        "mma.sync.aligned.m16n8k16.row.col.f32.bf16.bf16.f32 "
        "{%0,%1,%2,%3}, {%4,%5,%6,%7}, {%8,%9}, {%0,%1,%2,%3};"
        : "+f"(c[0]), "+f"(c[1]), "+f"(c[2]), "+f"(c[3])
        : "r"(a0), "r"(a1), "r"(a2), "r"(a3), "r"(b0), "r"(b1));
}

#define GBM 128
#define GBN 128
#define GBK 32
#define APITCH 20     // u32 per A row (16 data + 4 pad)
#define BPITCH 20     // u32 per B row

__global__ __launch_bounds__(256) void k_gemm_bf16(int Nrows) {
    __shared__ uint32_t Ash[GBM][APITCH];   // [m][kpair] hi
    __shared__ uint32_t Asl[GBM][APITCH];   // lo
    __shared__ uint32_t Bsh[GBN][BPITCH];   // [n][kpair, 16B-chunk swizzled] hi
    __shared__ uint32_t Bsl[GBN][BPITCH];   // lo

    const int tid  = threadIdx.x;
    const int lane = tid & 31;
    const int wid  = tid >> 5;
    const int warp_m = wid >> 2;        // 0..1
    const int warp_n = wid & 3;         // 0..3
    const int block_m = blockIdx.x * GBM;
    const int block_n = blockIdx.y * GBN;

    float acc[4][4][4];
    #pragma unroll
    for (int i = 0; i < 4; i++)
        #pragma unroll
        for (int j = 0; j < 4; j++)
            #pragma unroll
            for (int r = 0; r < 4; r++) acc[i][j][r] = 0.0f;

    // ---- Precomputed LDSM lane addressing (verified layout, R9) ----
    const uint32_t a_hi_base = smem_u32(&Ash[0][0]);
    const uint32_t a_lo_base = smem_u32(&Asl[0][0]);
    const uint32_t a_row = (uint32_t)(warp_m * 64 + (lane & 15)) * (APITCH * 4);
    const uint32_t a_ch  = (uint32_t)(lane >> 4) * 16;          // bytes
    const uint32_t b_hi_base = smem_u32(&Bsh[0][0]);
    const uint32_t b_lo_base = smem_u32(&Bsl[0][0]);
    const int b_nl  = (lane & 7) + ((lane >> 4) & 1) * 8;       // 0..15
    const int b_cha = (lane >> 3) & 1;                          // chunk +0/+1

    for (int k0 = 0; k0 < DIM; k0 += GBK) {
        // ---- A tile: 128 rows x 32 k bf16 = 512 uint4 per plane, 2/thread ----
        #pragma unroll
        for (int l = 0; l < 2; l++) {
            int idx = tid + l * 256;        // 0..511
            int row = idx >> 2;
            int q   = idx & 3;              // 16B chunk (8 bf16)
            int grow = block_m + row;
            uint4 hv = make_uint4(0, 0, 0, 0), lv = make_uint4(0, 0, 0, 0);
            if (grow < Nrows) {
                size_t off = (size_t)grow * DIM + k0 + q * 8;
                hv = *reinterpret_cast<const uint4*>(&g_Xh[off]);
                lv = *reinterpret_cast<const uint4*>(&g_Xl[off]);
            }
            *reinterpret_cast<uint4*>(&Ash[row][q * 4]) = hv;
            *reinterpret_cast<uint4*>(&Asl[row][q * 4]) = lv;
        }
        // ---- B tile: 128 n x 32 k bf16 from W^T, chunk-swizzled ----
        #pragma unroll
        for (int l = 0; l < 2; l++) {
            int idx = tid + l * 256;        // 0..511
            int n   = idx >> 2;             // 0..127
            int q   = idx & 3;
            size_t off = (size_t)(block_n + n) * DIM + k0 + q * 8;
            uint4 hv = *reinterpret_cast<const uint4*>(&g_Wh[off]);
            uint4 lv = *reinterpret_cast<const uint4*>(&g_Wl[off]);
            int ch = q ^ ((n >> 2) & 3);    // swizzled 16B chunk
            *reinterpret_cast<uint4*>(&Bsh[n][ch * 4]) = hv;
            *reinterpret_cast<uint4*>(&Bsl[n][ch * 4]) = lv;
        }
        __syncthreads();

        #pragma unroll
        for (int si = 0; si < 2; si++) {    // two k16 sub-iters per BK=32
            uint32_t fah[4][4], fal[4][4];
            #pragma unroll
            for (int mt = 0; mt < 4; mt++) {
                uint32_t off = a_row + (uint32_t)(mt * 16) * (APITCH * 4) + a_ch + (uint32_t)si * 32;
                ldsm_x4(fah[mt][0], fah[mt][1], fah[mt][2], fah[mt][3], a_hi_base + off);
                ldsm_x4(fal[mt][0], fal[mt][1], fal[mt][2], fal[mt][3], a_lo_base + off);
            }
            uint32_t fbh[4][2], fbl[4][2];
            #pragma unroll
            for (int ntp = 0; ntp < 2; ntp++) {
                int n = warp_n * 32 + ntp * 16 + b_nl;
                uint32_t chunk = (uint32_t)((2 * si + b_cha) ^ ((n >> 2) & 3));
                uint32_t off = (uint32_t)n * (BPITCH * 4) + chunk * 16;
                ldsm_x4(fbh[2 * ntp][0], fbh[2 * ntp][1], fbh[2 * ntp + 1][0], fbh[2 * ntp + 1][1],
                        b_hi_base + off);
                ldsm_x4(fbl[2 * ntp][0], fbl[2 * ntp][1], fbl[2 * ntp + 1][0], fbl[2 * ntp + 1][1],
                        b_lo_base + off);
            }
            #pragma unroll
            for (int mt = 0; mt < 4; mt++)
                #pragma unroll
                for (int nt = 0; nt < 4; nt++) {
                    mma_bf16(acc[mt][nt], fal[mt][0], fal[mt][1], fal[mt][2], fal[mt][3],
                             fbh[nt][0], fbh[nt][1]);
                    mma_bf16(acc[mt][nt], fah[mt][0], fah[mt][1], fah[mt][2], fah[mt][3],
                             fbl[nt][0], fbl[nt][1]);
                    mma_bf16(acc[mt][nt], fah[mt][0], fah[mt][1], fah[mt][2], fah[mt][3],
                             fbh[nt][0], fbh[nt][1]);
                }
        }
        __syncthreads();
    }

    // Epilogue: write 64x32 warp tile
    const int g  = lane >> 2;
    const int tg = lane & 3;
    #pragma unroll
    for (int mt = 0; mt < 4; mt++) {
        int r0 = block_m + warp_m * 64 + mt * 16 + g;
        #pragma unroll
        for (int nt = 0; nt < 4; nt++) {
            int c = block_n + warp_n * 32 + nt * 8 + 2 * tg;
            if (r0 < Nrows)
                *reinterpret_cast<float2*>(&g_support[(size_t)r0 * DIM + c]) =
                    make_float2(acc[mt][nt][0], acc[mt][nt][1]);
            if (r0 + 8 < Nrows)
                *reinterpret_cast<float2*>(&g_support[(size_t)(r0 + 8) * DIM + c]) =
                    make_float2(acc[mt][nt][2], acc[mt][nt][3]);
        }
    }
}

// ---------------- SpMM + fused L2 normalize ----------------
__global__ __launch_bounds__(DIM) void k_spmm_norm(float* __restrict__ out, int n) {
    const int row = blockIdx.x;
    if (row >= n) return;
    const int t = threadIdx.x;

    const int beg = g_rowptr[row];
    const int end = g_rowptr[row + 1];

    float a0 = 0.0f, a1 = 0.0f, a2 = 0.0f, a3 = 0.0f;
    int e = beg;
    for (; e + 3 < end; e += 4) {
        int   s0 = __ldg(&g_esrc[e]);
        int   s1 = __ldg(&g_esrc[e + 1]);
        int   s2 = __ldg(&g_esrc[e + 2]);
        int   s3 = __ldg(&g_esrc[e + 3]);
        float v0 = __ldg(&g_eval[e]);
        float v1 = __ldg(&g_eval[e + 1]);
        float v2 = __ldg(&g_eval[e + 2]);
        float v3 = __ldg(&g_eval[e + 3]);
        a0 = fmaf(v0, g_support[(size_t)s0 * DIM + t], a0);
        a1 = fmaf(v1, g_support[(size_t)s1 * DIM + t], a1);
        a2 = fmaf(v2, g_support[(size_t)s2 * DIM + t], a2);
        a3 = fmaf(v3, g_support[(size_t)s3 * DIM + t], a3);
    }
    for (; e < end; e++) {
        int   s0 = __ldg(&g_esrc[e]);
        float v0 = __ldg(&g_eval[e]);
        a0 = fmaf(v0, g_support[(size_t)s0 * DIM + t], a0);
    }
    float acc = (a0 + a1) + (a2 + a3);

    __shared__ float red[DIM];
    red[t] = acc * acc;
    __syncthreads();
    #pragma unroll
    for (int s = DIM / 2; s >= 32; s >>= 1) {
        if (t < s) red[t] += red[t + s];
        __syncthreads();
    }
    if (t < 32) {
        float w = red[t];
        #pragma unroll
        for (int o = 16; o > 0; o >>= 1) w += __shfl_down_sync(0xFFFFFFFF, w, o);
        if (t == 0) red[0] = w;
    }
    __syncthreads();
    float ss = red[0];

    float norm  = sqrtf(ss);
    float denom = fmaxf(norm, 1e-12f);
    out[(size_t)row * DIM + t] = acc / denom;
}

// ---------------- launch ----------------
extern "C" void kernel_launch(void* const* d_in, const int* in_sizes, int n_in,
                              void* d_out, int out_size) {
    const float* x  = (const float*)d_in[0];   // [N, 256]
    const float* W  = (const float*)d_in[1];   // [256, 256]
    const float* av = (const float*)d_in[2];   // [E]
    const float* aw = (const float*)d_in[3];   // [E]
    const int*   ei = (const int*)  d_in[4];   // [2, E]: dst row, then src row
    float* out = (float*)d_out;

    int N = in_sizes[0] / DIM;
    int E = in_sizes[2];
    const int* dst = ei;
    const int* src = ei + E;

    int nb = (N + SCANB - 1) / SCANB;
    int total8 = (N * DIM) / 8;

    // Pre-convert inputs to bf16 hi/lo (hoists conversion out of GEMM mainloop)
    k_convert_w<<<DIM, DIM>>>(W);
    k_convert_x<<<(total8 + 255) / 256, 256>>>(x, total8);

    // GEMM (independent of CSR build)
    dim3 ggrid((N + GBM - 1) / GBM, DIM / GBN);
    k_gemm_bf16<<<ggrid, 256>>>(N);

    // CSR build
    k_zero_counts<<<(N + 255) / 256, 256>>>(N);
    k_hist<<<(E + 255) / 256, 256>>>(dst, E);
    k_scan_block<<<nb, SCANB>>>(N);
    k_scan_sums<<<1, MAXBLK>>>(nb);
    k_finalize_rowptr<<<(N + 255) / 256, 256>>>(N);
    k_fill<<<(E + 255) / 256, 256>>>(dst, src, av, aw, E);

    // Aggregate + normalize
    k_spmm_norm<<<N, DIM>>>(out, N);
}

// round 11
// speedup vs baseline: 1.0909x; 1.0909x over previous
#include <cuda_runtime.h>
#include <cuda_bf16.h>
#include <math.h>
#include <stdint.h>

// Problem constants (shapes fixed by the dataset).
#define DIM   256
#define MAXN  100000
#define MAXE  800000
#define SCANB 1024
#define MAXBLK 128          // >= ceil(MAXN/SCANB) = 98

// -------- device-global scratch (allocation-free workaround) --------
__device__ float g_support[MAXN * DIM];   // x @ W
__device__ int   g_counts[MAXN];
__device__ int   g_scan[MAXN];
__device__ int   g_rowptr[MAXN + 1];
__device__ int   g_cursor[MAXN];
__device__ int   g_bsum[MAXBLK];
__device__ int   g_esrc[MAXE];
__device__ float g_eval[MAXE];

// ---------------- CSR construction ----------------
__global__ void k_zero_counts(int n) {
    int i = blockIdx.x * blockDim.x + threadIdx.x;
    if (i < n) g_counts[i] = 0;
}

__global__ void k_hist(const int* __restrict__ dst, int E) {
    int e = blockIdx.x * blockDim.x + threadIdx.x;
    if (e < E) atomicAdd(&g_counts[dst[e]], 1);
}

__global__ void k_scan_block(int n) {
    __shared__ int s[SCANB];
    int t = threadIdx.x;
    int gid = blockIdx.x * SCANB + t;
    int v = (gid < n) ? g_counts[gid] : 0;
    s[t] = v;
    __syncthreads();
    #pragma unroll
    for (int off = 1; off < SCANB; off <<= 1) {
        int x = (t >= off) ? s[t - off] : 0;
        __syncthreads();
        s[t] += x;
        __syncthreads();
    }
    if (gid < n) g_scan[gid] = s[t];
    if (t == SCANB - 1) g_bsum[blockIdx.x] = s[t];
}

__global__ void k_scan_sums(int nb) {
    __shared__ int s[MAXBLK];
    int t = threadIdx.x;                 // 128 threads
    int v = (t < nb) ? g_bsum[t] : 0;
    s[t] = v;
    __syncthreads();
    #pragma unroll
    for (int off = 1; off < MAXBLK; off <<= 1) {
        int x = (t >= off) ? s[t - off] : 0;
        __syncthreads();
        s[t] += x;
        __syncthreads();
    }
    if (t < nb) g_bsum[t] = s[t] - v;    // exclusive
}

__global__ void k_finalize_rowptr(int n) {
    int i = blockIdx.x * blockDim.x + threadIdx.x;
    if (i < n) {
        g_rowptr[i + 1] = g_scan[i] + g_bsum[i >> 10];
        int rp0 = (i == 0) ? 0 : (g_scan[i - 1] + g_bsum[(i - 1) >> 10]);
        g_cursor[i] = rp0;
        if (i == 0) g_rowptr[0] = 0;
    }
}

__global__ void k_fill(const int* __restrict__ dst, const int* __restrict__ src,
                       const float* __restrict__ av, const float* __restrict__ aw, int E) {
    int e = blockIdx.x * blockDim.x + threadIdx.x;
    if (e < E) {
        int d = dst[e];
        int p = atomicAdd(&g_cursor[d], 1);
        g_esrc[p] = src[e];
        g_eval[p] = av[e] + aw[e];
    }
}

// ---------------- GEMM: support = x @ W  (3xBF16 tensor-core, R7 layout) ----
// 128x128 block tile, BK=32, 256 threads = 8 warps in 2(M) x 4(N).
// Warp tile 64x32 = 4x4 m16n8k16 sub-tiles, bf16 hi/lo split (error ~2^-17).
// __launch_bounds__(256,2): cap 128 regs -> 2 CTAs/SM to hide sync/load latency.

__device__ __forceinline__ uint32_t pack_bf16(float a, float b) {
    __nv_bfloat162 h = __floats2bfloat162_rn(a, b);
    return *reinterpret_cast<uint32_t*>(&h);
}
__device__ __forceinline__ float bf16_hi_f(float a) {
    return __bfloat162float(__float2bfloat16_rn(a));
}

__device__ __forceinline__ void mma_bf16(float c[4], uint32_t a0, uint32_t a1,
                                         uint32_t a2, uint32_t a3,
                                         uint32_t b0, uint32_t b1) {
    asm volatile(
        "mma.sync.aligned.m16n8k16.row.col.f32.bf16.bf16.f32 "
        "{%0,%1,%2,%3}, {%4,%5,%6,%7}, {%8,%9}, {%0,%1,%2,%3};"
        : "+f"(c[0]), "+f"(c[1]), "+f"(c[2]), "+f"(c[3])
        : "r"(a0), "r"(a1), "r"(a2), "r"(a3), "r"(b0), "r"(b1));
}

#define GBM 128
#define GBN 128
#define GBK 32
#define KP  (GBK / 2)      // 16 k-pairs
#define A_PITCH 20         // u32 pitch ≡ 4 (mod 32): conflict-free A frag loads
#define B_PITCH 136        // u32 pitch ≡ 8 (mod 32): conflict-free B frag loads

__global__ __launch_bounds__(256, 2) void k_gemm_bf16(const float* __restrict__ X,
                                                      const float* __restrict__ W, int Nrows) {
    // Packed bf16x2 (pairs along k).
    __shared__ uint32_t Ash[GBM][A_PITCH];
    __shared__ uint32_t Asl[GBM][A_PITCH];
    __shared__ uint32_t Bsh[KP][B_PITCH];
    __shared__ uint32_t Bsl[KP][B_PITCH];

    const int tid  = threadIdx.x;
    const int lane = tid & 31;
    const int wid  = tid >> 5;
    const int warp_m = wid >> 2;        // 0..1
    const int warp_n = wid & 3;         // 0..3
    const int block_m = blockIdx.x * GBM;
    const int block_n = blockIdx.y * GBN;
    const int g  = lane >> 2;           // 0..7
    const int tg = lane & 3;            // 0..3

    float acc[4][4][4];
    #pragma unroll
    for (int i = 0; i < 4; i++)
        #pragma unroll
        for (int j = 0; j < 4; j++)
            #pragma unroll
            for (int r = 0; r < 4; r++) acc[i][j][r] = 0.0f;

    for (int k0 = 0; k0 < DIM; k0 += GBK) {
        // ---- Load A tile: 128 rows x 32 k = 1024 float4, 4 per thread ----
        #pragma unroll
        for (int l = 0; l < 4; l++) {
            int idx = tid + l * 256;        // 0..1023
            int r   = idx >> 3;             // 8 float4 per row
            int k4  = idx & 7;
            int grow = block_m + r;
            float4 a = make_float4(0.f, 0.f, 0.f, 0.f);
            if (grow < Nrows)
                a = *reinterpret_cast<const float4*>(&X[(size_t)grow * DIM + k0 + k4 * 4]);
            float hx = bf16_hi_f(a.x), hy = bf16_hi_f(a.y), hz = bf16_hi_f(a.z), hw = bf16_hi_f(a.w);
            Ash[r][2 * k4 + 0] = pack_bf16(hx, hy);
            Ash[r][2 * k4 + 1] = pack_bf16(hz, hw);
            Asl[r][2 * k4 + 0] = pack_bf16(a.x - hx, a.y - hy);
            Asl[r][2 * k4 + 1] = pack_bf16(a.z - hz, a.w - hw);
        }
        // ---- Load B tile: 32 k x 128 n, transposed into k-pair layout ----
        #pragma unroll
        for (int l = 0; l < 2; l++) {
            int idx = tid + l * 256;        // 0..511
            int kp  = idx >> 5;             // 0..15
            int n4  = idx & 31;
            float4 w0 = *reinterpret_cast<const float4*>(&W[(size_t)(k0 + 2 * kp)     * DIM + block_n + n4 * 4]);
            float4 w1 = *reinterpret_cast<const float4*>(&W[(size_t)(k0 + 2 * kp + 1) * DIM + block_n + n4 * 4]);
            float a0[4] = {w0.x, w0.y, w0.z, w0.w};
            float a1[4] = {w1.x, w1.y, w1.z, w1.w};
            #pragma unroll
            for (int j = 0; j < 4; j++) {
                float h0 = bf16_hi_f(a0[j]);
                float h1 = bf16_hi_f(a1[j]);
                Bsh[kp][n4 * 4 + j] = pack_bf16(h0, h1);
                Bsl[kp][n4 * 4 + j] = pack_bf16(a0[j] - h0, a1[j] - h1);
            }
        }
        __syncthreads();

        #pragma unroll
        for (int kc = 0; kc < KP; kc += 8) {   // two k16 chunks per BK=32
            uint32_t fah[4][4], fal[4][4];
            #pragma unroll
            for (int mt = 0; mt < 4; mt++) {
                int m = warp_m * 64 + mt * 16 + g;
                fah[mt][0] = Ash[m][kc + tg];
                fah[mt][1] = Ash[m + 8][kc + tg];
                fah[mt][2] = Ash[m][kc + tg + 4];
                fah[mt][3] = Ash[m + 8][kc + tg + 4];
                fal[mt][0] = Asl[m][kc + tg];
                fal[mt][1] = Asl[m + 8][kc + tg];
                fal[mt][2] = Asl[m][kc + tg + 4];
                fal[mt][3] = Asl[m + 8][kc + tg + 4];
            }
            uint32_t fbh[4][2], fbl[4][2];
            #pragma unroll
            for (int nt = 0; nt < 4; nt++) {
                int n = warp_n * 32 + nt * 8 + g;
                fbh[nt][0] = Bsh[kc + tg][n];
                fbh[nt][1] = Bsh[kc + tg + 4][n];
                fbl[nt][0] = Bsl[kc + tg][n];
                fbl[nt][1] = Bsl[kc + tg + 4][n];
            }
            #pragma unroll
            for (int mt = 0; mt < 4; mt++)
                #pragma unroll
                for (int nt = 0; nt < 4; nt++) {
                    mma_bf16(acc[mt][nt], fal[mt][0], fal[mt][1], fal[mt][2], fal[mt][3],
                             fbh[nt][0], fbh[nt][1]);
                    mma_bf16(acc[mt][nt], fah[mt][0], fah[mt][1], fah[mt][2], fah[mt][3],
                             fbl[nt][0], fbl[nt][1]);
                    mma_bf16(acc[mt][nt], fah[mt][0], fah[mt][1], fah[mt][2], fah[mt][3],
                             fbh[nt][0], fbh[nt][1]);
                }
        }
        __syncthreads();
    }

    // Epilogue: write 64x32 warp tile
    #pragma unroll
    for (int mt = 0; mt < 4; mt++) {
        int r0 = block_m + warp_m * 64 + mt * 16 + g;
        #pragma unroll
        for (int nt = 0; nt < 4; nt++) {
            int c = block_n + warp_n * 32 + nt * 8 + 2 * tg;
            if (r0 < Nrows)
                *reinterpret_cast<float2*>(&g_support[(size_t)r0 * DIM + c]) =
                    make_float2(acc[mt][nt][0], acc[mt][nt][1]);
            if (r0 + 8 < Nrows)
                *reinterpret_cast<float2*>(&g_support[(size_t)(r0 + 8) * DIM + c]) =
                    make_float2(acc[mt][nt][2], acc[mt][nt][3]);
        }
    }
}

// ---------------- SpMM + fused L2 normalize ----------------
__global__ __launch_bounds__(DIM) void k_spmm_norm(float* __restrict__ out, int n) {
    const int row = blockIdx.x;
    if (row >= n) return;
    const int t = threadIdx.x;

    const int beg = g_rowptr[row];
    const int end = g_rowptr[row + 1];

    float a0 = 0.0f, a1 = 0.0f, a2 = 0.0f, a3 = 0.0f;
    int e = beg;
    for (; e + 3 < end; e += 4) {
        int   s0 = __ldg(&g_esrc[e]);
        int   s1 = __ldg(&g_esrc[e + 1]);
        int   s2 = __ldg(&g_esrc[e + 2]);
        int   s3 = __ldg(&g_esrc[e + 3]);
        float v0 = __ldg(&g_eval[e]);
        float v1 = __ldg(&g_eval[e + 1]);
        float v2 = __ldg(&g_eval[e + 2]);
        float v3 = __ldg(&g_eval[e + 3]);
        a0 = fmaf(v0, g_support[(size_t)s0 * DIM + t], a0);
        a1 = fmaf(v1, g_support[(size_t)s1 * DIM + t], a1);
        a2 = fmaf(v2, g_support[(size_t)s2 * DIM + t], a2);
        a3 = fmaf(v3, g_support[(size_t)s3 * DIM + t], a3);
    }
    for (; e < end; e++) {
        int   s0 = __ldg(&g_esrc[e]);
        float v0 = __ldg(&g_eval[e]);
        a0 = fmaf(v0, g_support[(size_t)s0 * DIM + t], a0);
    }
    float acc = (a0 + a1) + (a2 + a3);

    __shared__ float red[DIM];
    red[t] = acc * acc;
    __syncthreads();
    #pragma unroll
    for (int s = DIM / 2; s >= 32; s >>= 1) {
        if (t < s) red[t] += red[t + s];
        __syncthreads();
    }
    if (t < 32) {
        float w = red[t];
        #pragma unroll
        for (int o = 16; o > 0; o >>= 1) w += __shfl_down_sync(0xFFFFFFFF, w, o);
        if (t == 0) red[0] = w;
    }
    __syncthreads();
    float ss = red[0];

    float norm  = sqrtf(ss);
    float denom = fmaxf(norm, 1e-12f);
    out[(size_t)row * DIM + t] = acc / denom;
}

// ---------------- launch ----------------
// Order puts the GEMM 6th so `ncu -s 5 -c 1` captures it (profiling aid;
// ordering is semantically equivalent — GEMM is independent of the CSR chain).
extern "C" void kernel_launch(void* const* d_in, const int* in_sizes, int n_in,
                              void* d_out, int out_size) {
    const float* x  = (const float*)d_in[0];   // [N, 256]
    const float* W  = (const float*)d_in[1];   // [256, 256]
    const float* av = (const float*)d_in[2];   // [E]
    const float* aw = (const float*)d_in[3];   // [E]
    const int*   ei = (const int*)  d_in[4];   // [2, E]: dst row, then src row
    float* out = (float*)d_out;

    int N = in_sizes[0] / DIM;
    int E = in_sizes[2];
    const int* dst = ei;
    const int* src = ei + E;

    int nb = (N + SCANB - 1) / SCANB;

    // CSR build (launches 1-5)
    k_zero_counts<<<(N + 255) / 256, 256>>>(N);
    k_hist<<<(E + 255) / 256, 256>>>(dst, E);
    k_scan_block<<<nb, SCANB>>>(N);
    k_scan_sums<<<1, MAXBLK>>>(nb);
    k_finalize_rowptr<<<(N + 255) / 256, 256>>>(N);

    // GEMM (launch 6 -> ncu capture target)
    dim3 ggrid((N + GBM - 1) / GBM, DIM / GBN);
    k_gemm_bf16<<<ggrid, 256>>>(x, W, N);

    // CSR fill (launch 7)
    k_fill<<<(E + 255) / 256, 256>>>(dst, src, av, aw, E);

    // Aggregate + normalize (launch 8)
    k_spmm_norm<<<N, DIM>>>(out, N);
}

// round 12
// speedup vs baseline: 1.1003x; 1.0086x over previous
#include <cuda_runtime.h>
#include <cuda_bf16.h>
#include <math.h>
#include <stdint.h>

// Problem constants (shapes fixed by the dataset).
#define DIM   256
#define MAXN  100000
#define MAXE  800000
#define SCANB 1024
#define MAXBLK 128          // >= ceil(MAXN/SCANB) = 98

// -------- device-global scratch (allocation-free workaround) --------
__device__ float g_support[MAXN * DIM];   // x @ W
__device__ int   g_counts[MAXN];
__device__ int   g_scan[MAXN];
__device__ int   g_rowptr[MAXN + 1];
__device__ int   g_cursor[MAXN];
__device__ int   g_bsum[MAXBLK];
__device__ int   g_esrc[MAXE];
__device__ float g_eval[MAXE];

// ---------------- CSR construction ----------------
__global__ void k_zero_counts(int n) {
    int i = blockIdx.x * blockDim.x + threadIdx.x;
    if (i < n) g_counts[i] = 0;
}

__global__ void k_hist(const int* __restrict__ dst, int E) {
    int e = blockIdx.x * blockDim.x + threadIdx.x;
    if (e < E) atomicAdd(&g_counts[dst[e]], 1);
}

__global__ void k_scan_block(int n) {
    __shared__ int s[SCANB];
    int t = threadIdx.x;
    int gid = blockIdx.x * SCANB + t;
    int v = (gid < n) ? g_counts[gid] : 0;
    s[t] = v;
    __syncthreads();
    #pragma unroll
    for (int off = 1; off < SCANB; off <<= 1) {
        int x = (t >= off) ? s[t - off] : 0;
        __syncthreads();
        s[t] += x;
        __syncthreads();
    }
    if (gid < n) g_scan[gid] = s[t];
    if (t == SCANB - 1) g_bsum[blockIdx.x] = s[t];
}

__global__ void k_scan_sums(int nb) {
    __shared__ int s[MAXBLK];
    int t = threadIdx.x;                 // 128 threads
    int v = (t < nb) ? g_bsum[t] : 0;
    s[t] = v;
    __syncthreads();
    #pragma unroll
    for (int off = 1; off < MAXBLK; off <<= 1) {
        int x = (t >= off) ? s[t - off] : 0;
        __syncthreads();
        s[t] += x;
        __syncthreads();
    }
    if (t < nb) g_bsum[t] = s[t] - v;    // exclusive
}

__global__ void k_finalize_rowptr(int n) {
    int i = blockIdx.x * blockDim.x + threadIdx.x;
    if (i < n) {
        g_rowptr[i + 1] = g_scan[i] + g_bsum[i >> 10];
        int rp0 = (i == 0) ? 0 : (g_scan[i - 1] + g_bsum[(i - 1) >> 10]);
        g_cursor[i] = rp0;
        if (i == 0) g_rowptr[0] = 0;
    }
}

__global__ void k_fill(const int* __restrict__ dst, const int* __restrict__ src,
                       const float* __restrict__ av, const float* __restrict__ aw, int E) {
    int e = blockIdx.x * blockDim.x + threadIdx.x;
    if (e < E) {
        int d = dst[e];
        int p = atomicAdd(&g_cursor[d], 1);
        g_esrc[p] = src[e];
        g_eval[p] = av[e] + aw[e];
    }
}

// ---------------- GEMM: support = x @ W  (3xBF16 tensor-core, R7-proven) ----
// 128x128 block tile, BK=32, 256 threads = 8 warps in 2(M) x 4(N).
// Warp tile 64x32 = 4x4 m16n8k16 sub-tiles, bf16 hi/lo split (error ~2^-17).

__device__ __forceinline__ uint32_t pack_bf16(float a, float b) {
    __nv_bfloat162 h = __floats2bfloat162_rn(a, b);
    return *reinterpret_cast<uint32_t*>(&h);
}
__device__ __forceinline__ float bf16_hi_f(float a) {
    return __bfloat162float(__float2bfloat16_rn(a));
}

__device__ __forceinline__ void mma_bf16(float c[4], uint32_t a0, uint32_t a1,
                                         uint32_t a2, uint32_t a3,
                                         uint32_t b0, uint32_t b1) {
    asm volatile(
        "mma.sync.aligned.m16n8k16.row.col.f32.bf16.bf16.f32 "
        "{%0,%1,%2,%3}, {%4,%5,%6,%7}, {%8,%9}, {%0,%1,%2,%3};"
        : "+f"(c[0]), "+f"(c[1]), "+f"(c[2]), "+f"(c[3])
        : "r"(a0), "r"(a1), "r"(a2), "r"(a3), "r"(b0), "r"(b1));
}

#define GBM 128
#define GBN 128
#define GBK 32
#define KP  (GBK / 2)      // 16 k-pairs
#define A_PITCH 20         // u32 pitch ≡ 4 (mod 32): conflict-free A frag loads
#define B_PITCH 136        // u32 pitch ≡ 8 (mod 32): conflict-free B frag loads

__global__ __launch_bounds__(256) void k_gemm_bf16(const float* __restrict__ X,
                                                   const float* __restrict__ W, int Nrows) {
    // Packed bf16x2 (pairs along k).
    __shared__ uint32_t Ash[GBM][A_PITCH];
    __shared__ uint32_t Asl[GBM][A_PITCH];
    __shared__ uint32_t Bsh[KP][B_PITCH];
    __shared__ uint32_t Bsl[KP][B_PITCH];

    const int tid  = threadIdx.x;
    const int lane = tid & 31;
    const int wid  = tid >> 5;
    const int warp_m = wid >> 2;        // 0..1
    const int warp_n = wid & 3;         // 0..3
    const int block_m = blockIdx.x * GBM;
    const int block_n = blockIdx.y * GBN;
    const int g  = lane >> 2;           // 0..7
    const int tg = lane & 3;            // 0..3

    float acc[4][4][4];
    #pragma unroll
    for (int i = 0; i < 4; i++)
        #pragma unroll
        for (int j = 0; j < 4; j++)
            #pragma unroll
            for (int r = 0; r < 4; r++) acc[i][j][r] = 0.0f;

    for (int k0 = 0; k0 < DIM; k0 += GBK) {
        // ---- Load A tile: 128 rows x 32 k = 1024 float4, 4 per thread ----
        #pragma unroll
        for (int l = 0; l < 4; l++) {
            int idx = tid + l * 256;        // 0..1023
            int r   = idx >> 3;             // 8 float4 per row
            int k4  = idx & 7;
            int grow = block_m + r;
            float4 a = make_float4(0.f, 0.f, 0.f, 0.f);
            if (grow < Nrows)
                a = *reinterpret_cast<const float4*>(&X[(size_t)grow * DIM + k0 + k4 * 4]);
            float hx = bf16_hi_f(a.x), hy = bf16_hi_f(a.y), hz = bf16_hi_f(a.z), hw = bf16_hi_f(a.w);
            Ash[r][2 * k4 + 0] = pack_bf16(hx, hy);
            Ash[r][2 * k4 + 1] = pack_bf16(hz, hw);
            Asl[r][2 * k4 + 0] = pack_bf16(a.x - hx, a.y - hy);
            Asl[r][2 * k4 + 1] = pack_bf16(a.z - hz, a.w - hw);
        }
        // ---- Load B tile: 32 k x 128 n, transposed into k-pair layout ----
        #pragma unroll
        for (int l = 0; l < 2; l++) {
            int idx = tid + l * 256;        // 0..511
            int kp  = idx >> 5;             // 0..15
            int n4  = idx & 31;
            float4 w0 = *reinterpret_cast<const float4*>(&W[(size_t)(k0 + 2 * kp)     * DIM + block_n + n4 * 4]);
            float4 w1 = *reinterpret_cast<const float4*>(&W[(size_t)(k0 + 2 * kp + 1) * DIM + block_n + n4 * 4]);
            float a0[4] = {w0.x, w0.y, w0.z, w0.w};
            float a1[4] = {w1.x, w1.y, w1.z, w1.w};
            #pragma unroll
            for (int j = 0; j < 4; j++) {
                float h0 = bf16_hi_f(a0[j]);
                float h1 = bf16_hi_f(a1[j]);
                Bsh[kp][n4 * 4 + j] = pack_bf16(h0, h1);
                Bsl[kp][n4 * 4 + j] = pack_bf16(a0[j] - h0, a1[j] - h1);
            }
        }
        __syncthreads();

        #pragma unroll
        for (int kc = 0; kc < KP; kc += 8) {   // two k16 chunks per BK=32
            uint32_t fah[4][4], fal[4][4];
            #pragma unroll
            for (int mt = 0; mt < 4; mt++) {
                int m = warp_m * 64 + mt * 16 + g;
                fah[mt][0] = Ash[m][kc + tg];
                fah[mt][1] = Ash[m + 8][kc + tg];
                fah[mt][2] = Ash[m][kc + tg + 4];
                fah[mt][3] = Ash[m + 8][kc + tg + 4];
                fal[mt][0] = Asl[m][kc + tg];
                fal[mt][1] = Asl[m + 8][kc + tg];
                fal[mt][2] = Asl[m][kc + tg + 4];
                fal[mt][3] = Asl[m + 8][kc + tg + 4];
            }
            uint32_t fbh[4][2], fbl[4][2];
            #pragma unroll
            for (int nt = 0; nt < 4; nt++) {
                int n = warp_n * 32 + nt * 8 + g;
                fbh[nt][0] = Bsh[kc + tg][n];
                fbh[nt][1] = Bsh[kc + tg + 4][n];
                fbl[nt][0] = Bsl[kc + tg][n];
                fbl[nt][1] = Bsl[kc + tg + 4][n];
            }
            #pragma unroll
            for (int mt = 0; mt < 4; mt++)
                #pragma unroll
                for (int nt = 0; nt < 4; nt++) {
                    mma_bf16(acc[mt][nt], fal[mt][0], fal[mt][1], fal[mt][2], fal[mt][3],
                             fbh[nt][0], fbh[nt][1]);
                    mma_bf16(acc[mt][nt], fah[mt][0], fah[mt][1], fah[mt][2], fah[mt][3],
                             fbl[nt][0], fbl[nt][1]);
                    mma_bf16(acc[mt][nt], fah[mt][0], fah[mt][1], fah[mt][2], fah[mt][3],
                             fbh[nt][0], fbh[nt][1]);
                }
        }
        __syncthreads();
    }

    // Epilogue: write 64x32 warp tile
    #pragma unroll
    for (int mt = 0; mt < 4; mt++) {
        int r0 = block_m + warp_m * 64 + mt * 16 + g;
        #pragma unroll
        for (int nt = 0; nt < 4; nt++) {
            int c = block_n + warp_n * 32 + nt * 8 + 2 * tg;
            if (r0 < Nrows)
                *reinterpret_cast<float2*>(&g_support[(size_t)r0 * DIM + c]) =
                    make_float2(acc[mt][nt][0], acc[mt][nt][1]);
            if (r0 + 8 < Nrows)
                *reinterpret_cast<float2*>(&g_support[(size_t)(r0 + 8) * DIM + c]) =
                    make_float2(acc[mt][nt][2], acc[mt][nt][3]);
        }
    }
}

// ---------------- SpMM + fused L2 normalize ----------------
__global__ __launch_bounds__(DIM) void k_spmm_norm(float* __restrict__ out, int n) {
    const int row = blockIdx.x;
    if (row >= n) return;
    const int t = threadIdx.x;

    const int beg = g_rowptr[row];
    const int end = g_rowptr[row + 1];

    float a0 = 0.0f, a1 = 0.0f, a2 = 0.0f, a3 = 0.0f;
    int e = beg;
    for (; e + 3 < end; e += 4) {
        int   s0 = __ldg(&g_esrc[e]);
        int   s1 = __ldg(&g_esrc[e + 1]);
        int   s2 = __ldg(&g_esrc[e + 2]);
        int   s3 = __ldg(&g_esrc[e + 3]);
        float v0 = __ldg(&g_eval[e]);
        float v1 = __ldg(&g_eval[e + 1]);
        float v2 = __ldg(&g_eval[e + 2]);
        float v3 = __ldg(&g_eval[e + 3]);
        a0 = fmaf(v0, g_support[(size_t)s0 * DIM + t], a0);
        a1 = fmaf(v1, g_support[(size_t)s1 * DIM + t], a1);
        a2 = fmaf(v2, g_support[(size_t)s2 * DIM + t], a2);
        a3 = fmaf(v3, g_support[(size_t)s3 * DIM + t], a3);
    }
    for (; e < end; e++) {
        int   s0 = __ldg(&g_esrc[e]);
        float v0 = __ldg(&g_eval[e]);
        a0 = fmaf(v0, g_support[(size_t)s0 * DIM + t], a0);
    }
    float acc = (a0 + a1) + (a2 + a3);

    __shared__ float red[DIM];
    red[t] = acc * acc;
    __syncthreads();
    #pragma unroll
    for (int s = DIM / 2; s >= 32; s >>= 1) {
        if (t < s) red[t] += red[t + s];
        __syncthreads();
    }
    if (t < 32) {
        float w = red[t];
        #pragma unroll
        for (int o = 16; o > 0; o >>= 1) w += __shfl_down_sync(0xFFFFFFFF, w, o);
        if (t == 0) red[0] = w;
    }
    __syncthreads();
    float ss = red[0];

    float norm  = sqrtf(ss);
    float denom = fmaxf(norm, 1e-12f);
    out[(size_t)row * DIM + t] = acc / denom;
}

// ---------------- launch ----------------
// GEMM placed as my 4th launch: empirically the ncu capture slot (R7/R10/R11
// all profiled launch #4). CSR internal order preserved; GEMM is independent,
// so this ordering is semantically identical.
extern "C" void kernel_launch(void* const* d_in, const int* in_sizes, int n_in,
                              void* d_out, int out_size) {
    const float* x  = (const float*)d_in[0];   // [N, 256]
    const float* W  = (const float*)d_in[1];   // [256, 256]
    const float* av = (const float*)d_in[2];   // [E]
    const float* aw = (const float*)d_in[3];   // [E]
    const int*   ei = (const int*)  d_in[4];   // [2, E]: dst row, then src row
    float* out = (float*)d_out;

    int N = in_sizes[0] / DIM;
    int E = in_sizes[2];
    const int* dst = ei;
    const int* src = ei + E;

    int nb = (N + SCANB - 1) / SCANB;

    // CSR launches 1-3
    k_zero_counts<<<(N + 255) / 256, 256>>>(N);
    k_hist<<<(E + 255) / 256, 256>>>(dst, E);
    k_scan_block<<<nb, SCANB>>>(N);

    // GEMM — launch #4 (ncu capture target)
    dim3 ggrid((N + GBM - 1) / GBM, DIM / GBN);
    k_gemm_bf16<<<ggrid, 256>>>(x, W, N);

    // CSR launches 5-7
    k_scan_sums<<<1, MAXBLK>>>(nb);
    k_finalize_rowptr<<<(N + 255) / 256, 256>>>(N);
    k_fill<<<(E + 255) / 256, 256>>>(dst, src, av, aw, E);

    // Aggregate + normalize (launch 8)
    k_spmm_norm<<<N, DIM>>>(out, N);
}

// round 14
// speedup vs baseline: 1.6145x; 1.4674x over previous
#include <cuda_runtime.h>
#include <cuda_bf16.h>
#include <math.h>
#include <stdint.h>

// Problem constants (shapes fixed by the dataset).
#define DIM   256
#define MAXN  100000
#define MAXE  800000
#define SCANB 1024
#define MAXBLK 128          // >= ceil(MAXN/SCANB) = 98

// -------- device-global scratch (allocation-free workaround) --------
__device__ float g_support[MAXN * DIM];   // x @ W
__device__ int   g_counts[MAXN];
__device__ int   g_scan[MAXN];
__device__ int   g_rowptr[MAXN + 1];
__device__ int   g_cursor[MAXN];
__device__ int   g_bsum[MAXBLK];
__device__ int   g_esrc[MAXE];
__device__ float g_eval[MAXE];

// ---------------- CSR construction ----------------
__global__ void k_zero_counts(int n) {
    int i = blockIdx.x * blockDim.x + threadIdx.x;
    if (i < n) g_counts[i] = 0;
}

__global__ void k_hist(const int* __restrict__ dst, int E) {
    int e = blockIdx.x * blockDim.x + threadIdx.x;
    if (e < E) atomicAdd(&g_counts[dst[e]], 1);
}

__global__ void k_scan_block(int n) {
    __shared__ int s[SCANB];
    int t = threadIdx.x;
    int gid = blockIdx.x * SCANB + t;
    int v = (gid < n) ? g_counts[gid] : 0;
    s[t] = v;
    __syncthreads();
    #pragma unroll
    for (int off = 1; off < SCANB; off <<= 1) {
        int x = (t >= off) ? s[t - off] : 0;
        __syncthreads();
        s[t] += x;
        __syncthreads();
    }
    if (gid < n) g_scan[gid] = s[t];
    if (t == SCANB - 1) g_bsum[blockIdx.x] = s[t];
}

__global__ void k_scan_sums(int nb) {
    __shared__ int s[MAXBLK];
    int t = threadIdx.x;                 // 128 threads
    int v = (t < nb) ? g_bsum[t] : 0;
    s[t] = v;
    __syncthreads();
    #pragma unroll
    for (int off = 1; off < MAXBLK; off <<= 1) {
        int x = (t >= off) ? s[t - off] : 0;
        __syncthreads();
        s[t] += x;
        __syncthreads();
    }
    if (t < nb) g_bsum[t] = s[t] - v;    // exclusive
}

__global__ void k_finalize_rowptr(int n) {
    int i = blockIdx.x * blockDim.x + threadIdx.x;
    if (i < n) {
        g_rowptr[i + 1] = g_scan[i] + g_bsum[i >> 10];
        int rp0 = (i == 0) ? 0 : (g_scan[i - 1] + g_bsum[(i - 1) >> 10]);
        g_cursor[i] = rp0;
        if (i == 0) g_rowptr[0] = 0;
    }
}

__global__ void k_fill(const int* __restrict__ dst, const int* __restrict__ src,
                       const float* __restrict__ av, const float* __restrict__ aw, int E) {
    int e = blockIdx.x * blockDim.x + threadIdx.x;
    if (e < E) {
        int d = dst[e];
        int p = atomicAdd(&g_cursor[d], 1);
        g_esrc[p] = src[e];
        g_eval[p] = av[e] + aw[e];
    }
}

// ---------------- GEMM: support = x @ W  (3xBF16 tensor-core, R7-proven) ----
// 128x128 block tile, BK=32, 256 threads = 8 warps in 2(M) x 4(N).
// Measured R12: 180us, 127 regs, 2 CTAs/SM, tensor 40.8%. Unchanged.

__device__ __forceinline__ uint32_t pack_bf16(float a, float b) {
    __nv_bfloat162 h = __floats2bfloat162_rn(a, b);
    return *reinterpret_cast<uint32_t*>(&h);
}
__device__ __forceinline__ float bf16_hi_f(float a) {
    return __bfloat162float(__float2bfloat16_rn(a));
}

__device__ __forceinline__ void mma_bf16(float c[4], uint32_t a0, uint32_t a1,
                                         uint32_t a2, uint32_t a3,
                                         uint32_t b0, uint32_t b1) {
    asm volatile(
        "mma.sync.aligned.m16n8k16.row.col.f32.bf16.bf16.f32 "
        "{%0,%1,%2,%3}, {%4,%5,%6,%7}, {%8,%9}, {%0,%1,%2,%3};"
        : "+f"(c[0]), "+f"(c[1]), "+f"(c[2]), "+f"(c[3])
        : "r"(a0), "r"(a1), "r"(a2), "r"(a3), "r"(b0), "r"(b1));
}

#define GBM 128
#define GBN 128
#define GBK 32
#define KP  (GBK / 2)      // 16 k-pairs
#define A_PITCH 20         // u32 pitch ≡ 4 (mod 32): conflict-free A frag loads
#define B_PITCH 136        // u32 pitch ≡ 8 (mod 32): conflict-free B frag loads

__global__ __launch_bounds__(256) void k_gemm_bf16(const float* __restrict__ X,
                                                   const float* __restrict__ W, int Nrows) {
    __shared__ uint32_t Ash[GBM][A_PITCH];
    __shared__ uint32_t Asl[GBM][A_PITCH];
    __shared__ uint32_t Bsh[KP][B_PITCH];
    __shared__ uint32_t Bsl[KP][B_PITCH];

    const int tid  = threadIdx.x;
    const int lane = tid & 31;
    const int wid  = tid >> 5;
    const int warp_m = wid >> 2;        // 0..1
    const int warp_n = wid & 3;         // 0..3
    const int block_m = blockIdx.x * GBM;
    const int block_n = blockIdx.y * GBN;
    const int g  = lane >> 2;           // 0..7
    const int tg = lane & 3;            // 0..3

    float acc[4][4][4];
    #pragma unroll
    for (int i = 0; i < 4; i++)
        #pragma unroll
        for (int j = 0; j < 4; j++)
            #pragma unroll
            for (int r = 0; r < 4; r++) acc[i][j][r] = 0.0f;

    for (int k0 = 0; k0 < DIM; k0 += GBK) {
        #pragma unroll
        for (int l = 0; l < 4; l++) {
            int idx = tid + l * 256;        // 0..1023
            int r   = idx >> 3;             // 8 float4 per row
            int k4  = idx & 7;
            int grow = block_m + r;
            float4 a = make_float4(0.f, 0.f, 0.f, 0.f);
            if (grow < Nrows)
                a = *reinterpret_cast<const float4*>(&X[(size_t)grow * DIM + k0 + k4 * 4]);
            float hx = bf16_hi_f(a.x), hy = bf16_hi_f(a.y), hz = bf16_hi_f(a.z), hw = bf16_hi_f(a.w);
            Ash[r][2 * k4 + 0] = pack_bf16(hx, hy);
            Ash[r][2 * k4 + 1] = pack_bf16(hz, hw);
            Asl[r][2 * k4 + 0] = pack_bf16(a.x - hx, a.y - hy);
            Asl[r][2 * k4 + 1] = pack_bf16(a.z - hz, a.w - hw);
        }
        #pragma unroll
        for (int l = 0; l < 2; l++) {
            int idx = tid + l * 256;        // 0..511
            int kp  = idx >> 5;             // 0..15
            int n4  = idx & 31;
            float4 w0 = *reinterpret_cast<const float4*>(&W[(size_t)(k0 + 2 * kp)     * DIM + block_n + n4 * 4]);
            float4 w1 = *reinterpret_cast<const float4*>(&W[(size_t)(k0 + 2 * kp + 1) * DIM + block_n + n4 * 4]);
            float a0[4] = {w0.x, w0.y, w0.z, w0.w};
            float a1[4] = {w1.x, w1.y, w1.z, w1.w};
            #pragma unroll
            for (int j = 0; j < 4; j++) {
                float h0 = bf16_hi_f(a0[j]);
                float h1 = bf16_hi_f(a1[j]);
                Bsh[kp][n4 * 4 + j] = pack_bf16(h0, h1);
                Bsl[kp][n4 * 4 + j] = pack_bf16(a0[j] - h0, a1[j] - h1);
            }
        }
        __syncthreads();

        #pragma unroll
        for (int kc = 0; kc < KP; kc += 8) {   // two k16 chunks per BK=32
            uint32_t fah[4][4], fal[4][4];
            #pragma unroll
            for (int mt = 0; mt < 4; mt++) {
                int m = warp_m * 64 + mt * 16 + g;
                fah[mt][0] = Ash[m][kc + tg];
                fah[mt][1] = Ash[m + 8][kc + tg];
                fah[mt][2] = Ash[m][kc + tg + 4];
                fah[mt][3] = Ash[m + 8][kc + tg + 4];
                fal[mt][0] = Asl[m][kc + tg];
                fal[mt][1] = Asl[m + 8][kc + tg];
                fal[mt][2] = Asl[m][kc + tg + 4];
                fal[mt][3] = Asl[m + 8][kc + tg + 4];
            }
            uint32_t fbh[4][2], fbl[4][2];
            #pragma unroll
            for (int nt = 0; nt < 4; nt++) {
                int n = warp_n * 32 + nt * 8 + g;
                fbh[nt][0] = Bsh[kc + tg][n];
                fbh[nt][1] = Bsh[kc + tg + 4][n];
                fbl[nt][0] = Bsl[kc + tg][n];
                fbl[nt][1] = Bsl[kc + tg + 4][n];
            }
            #pragma unroll
            for (int mt = 0; mt < 4; mt++)
                #pragma unroll
                for (int nt = 0; nt < 4; nt++) {
                    mma_bf16(acc[mt][nt], fal[mt][0], fal[mt][1], fal[mt][2], fal[mt][3],
                             fbh[nt][0], fbh[nt][1]);
                    mma_bf16(acc[mt][nt], fah[mt][0], fah[mt][1], fah[mt][2], fah[mt][3],
                             fbl[nt][0], fbl[nt][1]);
                    mma_bf16(acc[mt][nt], fah[mt][0], fah[mt][1], fah[mt][2], fah[mt][3],
                             fbh[nt][0], fbh[nt][1]);
                }
        }
        __syncthreads();
    }

    #pragma unroll
    for (int mt = 0; mt < 4; mt++) {
        int r0 = block_m + warp_m * 64 + mt * 16 + g;
        #pragma unroll
        for (int nt = 0; nt < 4; nt++) {
            int c = block_n + warp_n * 32 + nt * 8 + 2 * tg;
            if (r0 < Nrows)
                *reinterpret_cast<float2*>(&g_support[(size_t)r0 * DIM + c]) =
                    make_float2(acc[mt][nt][0], acc[mt][nt][1]);
            if (r0 + 8 < Nrows)
                *reinterpret_cast<float2*>(&g_support[(size_t)(r0 + 8) * DIM + c]) =
                    make_float2(acc[mt][nt][2], acc[mt][nt][3]);
        }
    }
}

// ---------------- SpMM + fused L2 normalize (warp-per-row) ----------------
// One warp owns one output row. Lane l holds cols {4l..4l+3} and {128+4l..}.
// Per edge: 2 coalesced float4 gathers. Norm reduction is a register
// butterfly — no smem, no __syncthreads.
__global__ __launch_bounds__(256) void k_spmm_norm(float* __restrict__ out, int n) {
    const int lane = threadIdx.x & 31;
    const int row  = blockIdx.x * 8 + (threadIdx.x >> 5);
    if (row >= n) return;

    const int beg = g_rowptr[row];
    const int end = g_rowptr[row + 1];

    float4 p0 = make_float4(0.f, 0.f, 0.f, 0.f);
    float4 p1 = make_float4(0.f, 0.f, 0.f, 0.f);
    float4 q0 = make_float4(0.f, 0.f, 0.f, 0.f);
    float4 q1 = make_float4(0.f, 0.f, 0.f, 0.f);

    int e = beg;
    for (; e + 1 < end; e += 2) {
        int   s0 = __ldg(&g_esrc[e]);
        int   s1 = __ldg(&g_esrc[e + 1]);
        float v0 = __ldg(&g_eval[e]);
        float v1 = __ldg(&g_eval[e + 1]);
        const float4* r0 = reinterpret_cast<const float4*>(&g_support[(size_t)s0 * DIM]);
        const float4* r1 = reinterpret_cast<const float4*>(&g_support[(size_t)s1 * DIM]);
        float4 x0 = r0[lane];
        float4 x1 = r0[lane + 32];
        float4 y0 = r1[lane];
        float4 y1 = r1[lane + 32];
        p0.x = fmaf(v0, x0.x, p0.x); p0.y = fmaf(v0, x0.y, p0.y);
        p0.z = fmaf(v0, x0.z, p0.z); p0.w = fmaf(v0, x0.w, p0.w);
        p1.x = fmaf(v0, x1.x, p1.x); p1.y = fmaf(v0, x1.y, p1.y);
        p1.z = fmaf(v0, x1.z, p1.z); p1.w = fmaf(v0, x1.w, p1.w);
        q0.x = fmaf(v1, y0.x, q0.x); q0.y = fmaf(v1, y0.y, q0.y);
        q0.z = fmaf(v1, y0.z, q0.z); q0.w = fmaf(v1, y0.w, q0.w);
        q1.x = fmaf(v1, y1.x, q1.x); q1.y = fmaf(v1, y1.y, q1.y);
        q1.z = fmaf(v1, y1.z, q1.z); q1.w = fmaf(v1, y1.w, q1.w);
    }
    if (e < end) {
        int   s0 = __ldg(&g_esrc[e]);
        float v0 = __ldg(&g_eval[e]);
        const float4* r0 = reinterpret_cast<const float4*>(&g_support[(size_t)s0 * DIM]);
        float4 x0 = r0[lane];
        float4 x1 = r0[lane + 32];
        p0.x = fmaf(v0, x0.x, p0.x); p0.y = fmaf(v0, x0.y, p0.y);
        p0.z = fmaf(v0, x0.z, p0.z); p0.w = fmaf(v0, x0.w, p0.w);
        p1.x = fmaf(v0, x1.x, p1.x); p1.y = fmaf(v0, x1.y, p1.y);
        p1.z = fmaf(v0, x1.z, p1.z); p1.w = fmaf(v0, x1.w, p1.w);
    }
    float4 a0 = make_float4(p0.x + q0.x, p0.y + q0.y, p0.z + q0.z, p0.w + q0.w);
    float4 a1 = make_float4(p1.x + q1.x, p1.y + q1.y, p1.z + q1.z, p1.w + q1.w);

    // L2 norm over the row: per-lane partial, then 5-step butterfly.
    float ss = a0.x * a0.x + a0.y * a0.y + a0.z * a0.z + a0.w * a0.w
             + a1.x * a1.x + a1.y * a1.y + a1.z * a1.z + a1.w * a1.w;
    #pragma unroll
    for (int o = 16; o > 0; o >>= 1)
        ss += __shfl_xor_sync(0xFFFFFFFF, ss, o);

    float inv = 1.0f / fmaxf(sqrtf(ss), 1e-12f);
    float4* dst = reinterpret_cast<float4*>(&out[(size_t)row * DIM]);
    dst[lane]      = make_float4(a0.x * inv, a0.y * inv, a0.z * inv, a0.w * inv);
    dst[lane + 32] = make_float4(a1.x * inv, a1.y * inv, a1.z * inv, a1.w * inv);
}

// ---------------- launch ----------------
extern "C" void kernel_launch(void* const* d_in, const int* in_sizes, int n_in,
                              void* d_out, int out_size) {
    const float* x  = (const float*)d_in[0];   // [N, 256]
    const float* W  = (const float*)d_in[1];   // [256, 256]
    const float* av = (const float*)d_in[2];   // [E]
    const float* aw = (const float*)d_in[3];   // [E]
    const int*   ei = (const int*)  d_in[4];   // [2, E]: dst row, then src row
    float* out = (float*)d_out;

    int N = in_sizes[0] / DIM;
    int E = in_sizes[2];
    const int* dst = ei;
    const int* src = ei + E;

    int nb = (N + SCANB - 1) / SCANB;

    // CSR launches 1-3
    k_zero_counts<<<(N + 255) / 256, 256>>>(N);
    k_hist<<<(E + 255) / 256, 256>>>(dst, E);
    k_scan_block<<<nb, SCANB>>>(N);

    // GEMM — launch #4 (ncu capture slot)
    dim3 ggrid((N + GBM - 1) / GBM, DIM / GBN);
    k_gemm_bf16<<<ggrid, 256>>>(x, W, N);

    // CSR launches 5-7
    k_scan_sums<<<1, MAXBLK>>>(nb);
    k_finalize_rowptr<<<(N + 255) / 256, 256>>>(N);
    k_fill<<<(E + 255) / 256, 256>>>(dst, src, av, aw, E);

    // Aggregate + normalize (warp-per-row)
    k_spmm_norm<<<(N + 7) / 8, 256>>>(out, N);
}